// round 16
// baseline (speedup 1.0000x reference)
#include <cuda_runtime.h>
#include <cuda_bf16.h>
#include <math.h>
#include <cstdint>

#define BB 256
#define TT 500
#define II 256
#define HH 512
#define GG 2048
#define OO 100
#define NBLK 128

typedef unsigned long long ull;

// ------------------------- global scratch (no allocs) -----------------------
__device__ float g_xg[(size_t)TT * BB * GG];            // [T][B][4H]
__device__ __nv_bfloat16 g_xs[(size_t)TT * BB * 512];   // [t*B+b][k]: k<256 x1, >=256 x2
__device__ __nv_bfloat16 g_Wxs[GG * 512];               // [n][k]: k<256 Wx1, >=256 Wx2
__device__ uint4 g_Wfrag[32 * 64 * 4 * 32];             // [bn][kt(0-31 W1,32-63 W2)][nt][lane]
__device__ uint4 g_hfrag[2][64 * 16 * 32];              // [buf][kt(0-31 h1,32-63 h2)][mt][lane]
__device__ float g_hfp[BB * HH];                        // fp32 h (for fc)
__device__ unsigned g_barc[4 * 32];                     // 4 group counters, 128B apart

// ------------------------- helpers ------------------------------------------
__device__ __forceinline__ float sigm(float x) { return 1.0f / (1.0f + __expf(-x)); }
__device__ __forceinline__ float tanh_fast(float x) { return 1.0f - 2.0f / (1.0f + __expf(2.0f * x)); }
__device__ __forceinline__ uint32_t smem_u32(const void* p) {
    return (uint32_t)__cvta_generic_to_shared(p);
}
__device__ __forceinline__ void ldsm4(uint32_t& a0, uint32_t& a1, uint32_t& a2, uint32_t& a3,
                                      uint32_t addr) {
    asm volatile("ldmatrix.sync.aligned.m8n8.x4.shared.b16 {%0,%1,%2,%3}, [%4];"
                 : "=r"(a0), "=r"(a1), "=r"(a2), "=r"(a3) : "r"(addr));
}
__device__ __forceinline__ void mma_bf16(float* d, uint32_t a0, uint32_t a1, uint32_t a2,
                                         uint32_t a3, uint32_t b0, uint32_t b1) {
    asm volatile(
        "mma.sync.aligned.m16n8k16.row.col.f32.bf16.bf16.f32 "
        "{%0,%1,%2,%3}, {%4,%5,%6,%7}, {%8,%9}, {%0,%1,%2,%3};"
        : "+f"(d[0]), "+f"(d[1]), "+f"(d[2]), "+f"(d[3])
        : "r"(a0), "r"(a1), "r"(a2), "r"(a3), "r"(b0), "r"(b1));
}
__device__ __forceinline__ uint32_t pack_bf2(float a, float b) {
    __nv_bfloat162 v = __halves2bfloat162(__float2bfloat16(a), __float2bfloat16(b));
    return *reinterpret_cast<uint32_t*>(&v);
}

// ---------------------------------------------------------------------------
// Prep A: split x into g_xs (transposed to [t*B+b] row order)
// ---------------------------------------------------------------------------
__global__ __launch_bounds__(256) void xsplit_kernel(const float* __restrict__ x) {
    const int total = TT * BB * 64;
    const int stride = gridDim.x * blockDim.x;
    for (int idx = blockIdx.x * blockDim.x + threadIdx.x; idx < total; idx += stride) {
        int r = idx >> 6;
        int q = idx & 63;
        int t = r >> 8;
        int b = r & 255;
        float4 v = *(const float4*)(x + ((size_t)b * TT + t) * II + q * 4);
        float r0, r1, r2, r3;
        __nv_bfloat162 h01, h23;
        {
            __nv_bfloat16 p0 = __float2bfloat16(v.x), p1 = __float2bfloat16(v.y);
            __nv_bfloat16 p2 = __float2bfloat16(v.z), p3 = __float2bfloat16(v.w);
            r0 = v.x - __bfloat162float(p0); r1 = v.y - __bfloat162float(p1);
            r2 = v.z - __bfloat162float(p2); r3 = v.w - __bfloat162float(p3);
            h01 = __halves2bfloat162(p0, p1); h23 = __halves2bfloat162(p2, p3);
        }
        __nv_bfloat16* row = g_xs + (size_t)r * 512;
        *(__nv_bfloat162*)(row + q * 4)     = h01;
        *(__nv_bfloat162*)(row + q * 4 + 2) = h23;
        *(__nv_bfloat162*)(row + 256 + q * 4)     = __halves2bfloat162(__float2bfloat16(r0), __float2bfloat16(r1));
        *(__nv_bfloat162*)(row + 256 + q * 4 + 2) = __halves2bfloat162(__float2bfloat16(r2), __float2bfloat16(r3));
    }
}

// ---------------------------------------------------------------------------
// Prep B: Wh -> fragment-major g_Wfrag (unchanged layout, validated R8-R15),
// Wx -> g_Wxs, zero g_hfrag, reset group barriers.
// ---------------------------------------------------------------------------
__global__ __launch_bounds__(256) void prep_kernel(const float* __restrict__ Wh,
                                                   const float* __restrict__ Wx) {
    const int stride = gridDim.x * blockDim.x;
    const int tid0 = blockIdx.x * blockDim.x + threadIdx.x;

    for (int idx = tid0; idx < 32 * 64 * 4 * 32 * 4; idx += stride) {
        int reg = idx & 3, lane = (idx >> 2) & 31, nt = (idx >> 7) & 3;
        int kt = (idx >> 9) & 63, bn = idx >> 15;
        int nl = nt * 16 + (reg & 1) * 8 + (lane >> 2);
        int kk = (kt & 31) * 16 + ((reg >> 1) & 1) * 8 + 2 * (lane & 3);
        int gate = (nl >> 3) & 3;
        int hidl = ((nl >> 5) << 3) + (nl & 7);
        int gcol = (gate << 9) + (bn << 4) + hidl;
        float w0 = Wh[(size_t)gcol * HH + kk];
        float w1 = Wh[(size_t)gcol * HH + kk + 1];
        __nv_bfloat16 h0 = __float2bfloat16(w0), h1 = __float2bfloat16(w1);
        __nv_bfloat162 v;
        if (kt < 32) v = __halves2bfloat162(h0, h1);
        else v = __halves2bfloat162(__float2bfloat16(w0 - __bfloat162float(h0)),
                                    __float2bfloat16(w1 - __bfloat162float(h1)));
        reinterpret_cast<__nv_bfloat162*>(g_Wfrag)[idx] = v;
    }

    for (int idx = tid0; idx < GG * II; idx += stride) {
        int n = idx >> 8, k = idx & 255;
        float w = Wx[idx];
        __nv_bfloat16 w1 = __float2bfloat16(w);
        g_Wxs[(size_t)n * 512 + k] = w1;
        g_Wxs[(size_t)n * 512 + 256 + k] = __float2bfloat16(w - __bfloat162float(w1));
    }

    for (int idx = tid0; idx < 2 * 64 * 16 * 32; idx += stride)
        reinterpret_cast<uint4*>(g_hfrag)[idx] = make_uint4(0, 0, 0, 0);

    if (tid0 < 4 * 32) g_barc[tid0] = 0;
}

// ---------------------------------------------------------------------------
// Kernel 1: xg = x @ Wx^T + bx + bh via HMMA 3-term split (round-9, PASS)
// ---------------------------------------------------------------------------
#define XPAD 72
#define XCHUNK (128 * XPAD * 2)
#define SMEM_XG (4 * XCHUNK)

__global__ __launch_bounds__(256, 1) void xg_hmma(const float* __restrict__ bx,
                                                  const float* __restrict__ bh) {
    extern __shared__ char smem[];
    const int tid = threadIdx.x;
    const int wid = tid >> 5;
    const int lane = tid & 31;
    const int wm = wid & 3;
    const int wn = wid >> 2;
    const int lr = lane & 15;
    const int khalf = lane >> 4;
    const int qp = lane >> 2;
    const int t4 = lane & 3;

    const size_t mBase = (size_t)blockIdx.x * 128;
    const int nBase = blockIdx.y * 128;

    const uint32_t aS[2] = { smem_u32(smem), smem_u32(smem) + XCHUNK };
    const uint32_t bS[2] = { aS[0] + 2 * XCHUNK, aS[0] + 3 * XCHUNK };

    float2 biasv[8];
#pragma unroll
    for (int nb = 0; nb < 8; nb++) {
        int col = nBase + wn * 64 + nb * 8 + 2 * t4;
        biasv[nb] = make_float2(bx[col] + bh[col], bx[col + 1] + bh[col + 1]);
    }

    float acc[2][8][4] = {};
    uint4 pfA[4], pfB[4];

    auto aCol = [](int c) { return ((c >> 2) == 1 ? 256 : 0) + (c & 3) * 64; };
    auto bCol = [](int c) { return ((c >> 2) == 2 ? 256 : 0) + (c & 3) * 64; };

#pragma unroll
    for (int j = 0; j < 4; j++) {
        int u = tid + j * 256;
        int n = u >> 3, q = u & 7;
        pfA[j] = *(const uint4*)(g_xs + (mBase + n) * 512 + aCol(0) + q * 8);
        pfB[j] = *(const uint4*)(g_Wxs + (size_t)(nBase + n) * 512 + bCol(0) + q * 8);
    }
#pragma unroll
    for (int j = 0; j < 4; j++) {
        int u = tid + j * 256;
        int n = u >> 3, q = u & 7;
        *(uint4*)(smem + (size_t)n * (XPAD * 2) + q * 16) = pfA[j];
        *(uint4*)(smem + 2 * XCHUNK + (size_t)n * (XPAD * 2) + q * 16) = pfB[j];
    }
    __syncthreads();

    for (int c = 0; c < 12; c++) {
        const int st = c & 1;
        if (c < 11) {
#pragma unroll
            for (int j = 0; j < 4; j++) {
                int u = tid + j * 256;
                int n = u >> 3, q = u & 7;
                pfA[j] = *(const uint4*)(g_xs + (mBase + n) * 512 + aCol(c + 1) + q * 8);
                pfB[j] = *(const uint4*)(g_Wxs + (size_t)(nBase + n) * 512 + bCol(c + 1) + q * 8);
            }
        }
#pragma unroll
        for (int k16 = 0; k16 < 4; k16++) {
            uint32_t a[2][4];
#pragma unroll
            for (int mi = 0; mi < 2; mi++) {
                uint32_t addr = aS[st] + (uint32_t)(wm * 32 + mi * 16 + lr) * (XPAD * 2)
                                + k16 * 32 + khalf * 16;
                ldsm4(a[mi][0], a[mi][1], a[mi][2], a[mi][3], addr);
            }
#pragma unroll
            for (int p = 0; p < 4; p++) {
                uint32_t b0, b1, b2, b3;
                uint32_t addr = bS[st] + (uint32_t)(wn * 64 + p * 16 + lr) * (XPAD * 2)
                                + k16 * 32 + khalf * 16;
                ldsm4(b0, b1, b2, b3, addr);
#pragma unroll
                for (int mi = 0; mi < 2; mi++) {
                    mma_bf16(acc[mi][2 * p],     a[mi][0], a[mi][1], a[mi][2], a[mi][3], b0, b2);
                    mma_bf16(acc[mi][2 * p + 1], a[mi][0], a[mi][1], a[mi][2], a[mi][3], b1, b3);
                }
            }
        }
        if (c < 11) {
            const int ns = (c + 1) & 1;
#pragma unroll
            for (int j = 0; j < 4; j++) {
                int u = tid + j * 256;
                int n = u >> 3, q = u & 7;
                *(uint4*)(smem + (size_t)ns * XCHUNK + (size_t)n * (XPAD * 2) + q * 16) = pfA[j];
                *(uint4*)(smem + 2 * XCHUNK + (size_t)ns * XCHUNK + (size_t)n * (XPAD * 2) + q * 16) = pfB[j];
            }
            __syncthreads();
        }
    }

#pragma unroll
    for (int mi = 0; mi < 2; mi++) {
#pragma unroll
        for (int rr = 0; rr < 2; rr++) {
            size_t row = mBase + wm * 32 + mi * 16 + qp + rr * 8;
            float* orow = g_xg + row * GG + nBase + wn * 64;
#pragma unroll
            for (int nb = 0; nb < 8; nb++) {
                float2 o = make_float2(acc[mi][nb][2 * rr] + biasv[nb].x,
                                       acc[mi][nb][2 * rr + 1] + biasv[nb].y);
                *(float2*)(orow + nb * 8 + 2 * t4) = o;
            }
        }
    }
}

// ---------------------------------------------------------------------------
// Kernel 2: persistent HMMA LSTM recurrence v8 = R14 split-k mainloop
// (A deduplicated: 128KB L2 traffic/block/step instead of 512KB) +
// R15 IVALL-free barrier (B weight fragments stay L1-resident; L1 = 228-72
// smem = 156KB > 128KB of B).
// 128 blocks x 512 threads. Block (bm, bn): 64 batch rows x 64 gate-cols.
// Warp (wm 0..3, wq 0..3): M16 tile wm, FULL N64, kt range [wq*8, wq*8+8).
// Per kt: 2 A ldg.cg + 8 B ld (L1 hits) + 24 MMA into 8 independent quads.
// Split-k partials reduced through 72KB smem at pointwise.
// Group barrier per bm (32 blocks): red.release.gpu + volatile poll.
// ---------------------------------------------------------------------------
#define SGROW 18
#define SMEM_LSTM (4 * 4 * 64 * SGROW * 4)   // 73728 B

__global__ __launch_bounds__(512, 1) void lstm_hmma() {
    extern __shared__ float sgp[];   // [wq][gate][row][SGROW]

    const int tid = threadIdx.x;
    const int lane = tid & 31;
    const int wid = tid >> 5;
    const int wm = wid & 3;
    const int wq = wid >> 2;
    const int qp = lane >> 2;
    const int t4 = lane & 3;

    const int bm = blockIdx.x >> 5;
    const int bn = blockIdx.x & 31;
    const int m0 = bm << 6;
    const int j0 = bn << 4;
    const int mt = bm * 4 + wm;
    const int ktb = wq * 8;          // this warp's kt base

    const int prow = tid >> 3;
    const int pv = tid & 7;
    const int grow = m0 + prow;
    const int ghid = j0 + 2 * pv;
    const int pmt = bm * 4 + (prow >> 4);
    const int r16 = prow & 15;
    const int comp = (r16 >> 3) + 2 * (pv >> 2);
    const int plane = (r16 & 7) * 4 + (pv & 3);

    unsigned* barp = &g_barc[bm * 32];

    float c0 = 0.f, c1 = 0.f;

    for (int t = 0; t < TT; ++t) {
        const int rb = t & 1;
        const uint4* Af = g_hfrag[rb] + (size_t)mt * 32 + lane;  // + kt*512

        // xg prefetch (DRAM), consumed at pointwise
        float2 xv[4];
#pragma unroll
        for (int g = 0; g < 4; g++)
            xv[g] = __ldcg((const float2*)(g_xg + ((size_t)t * BB + grow) * GG + (g << 9) + ghid));

        // A queue depth 4 (h1 + h2), covering this warp's kt range
        uint4 a1q[4], a2q[4];
#pragma unroll
        for (int j = 0; j < 4; j++) {
            a1q[j] = __ldcg(Af + (size_t)(ktb + j) * 512);
            a2q[j] = __ldcg(Af + (size_t)(ktb + j + 32) * 512);
        }

        // 8 independent acc quads: [nt][p]
        float acc[4][2][4] = {};

#pragma unroll
        for (int kt = 0; kt < 8; kt++) {
            uint4 A1 = a1q[kt & 3], A2 = a2q[kt & 3];
            if (kt < 4) {
                a1q[kt & 3] = __ldcg(Af + (size_t)(ktb + kt + 4) * 512);
                a2q[kt & 3] = __ldcg(Af + (size_t)(ktb + kt + 36) * 512);
            }
            const uint4* wbase = g_Wfrag + (((size_t)bn * 64 + ktb + kt) * 4) * 32 + lane;
#pragma unroll
            for (int nt = 0; nt < 4; nt++) {
                uint4 B1 = wbase[nt * 32];               // L1-resident now
                uint4 B2 = wbase[32 * 4 * 32 + nt * 32];
                mma_bf16(acc[nt][0], A1.x, A1.y, A1.z, A1.w, B1.x, B1.z);
                mma_bf16(acc[nt][1], A1.x, A1.y, A1.z, A1.w, B1.y, B1.w);
                mma_bf16(acc[nt][0], A1.x, A1.y, A1.z, A1.w, B2.x, B2.z);
                mma_bf16(acc[nt][1], A1.x, A1.y, A1.z, A1.w, B2.y, B2.w);
                mma_bf16(acc[nt][0], A2.x, A2.y, A2.z, A2.w, B1.x, B1.z);
                mma_bf16(acc[nt][1], A2.x, A2.y, A2.z, A2.w, B1.y, B1.w);
            }
        }

        // stage split-k partial gates to smem: gate=(2nt+p)&3, hid base (nt>>1)*8
#pragma unroll
        for (int nt = 0; nt < 4; nt++) {
#pragma unroll
            for (int p = 0; p < 2; p++) {
                int gate = (2 * nt + p) & 3;
                int hidb = ((nt >> 1) << 3) + 2 * t4;
                float* s0 = &sgp[((wq * 4 + gate) * 64 + wm * 16 + qp) * SGROW + hidb];
                *(float2*)s0 = make_float2(acc[nt][p][0], acc[nt][p][1]);
                float* s1 = &sgp[((wq * 4 + gate) * 64 + wm * 16 + qp + 8) * SGROW + hidb];
                *(float2*)s1 = make_float2(acc[nt][p][2], acc[nt][p][3]);
            }
        }
        __syncthreads();

        // pointwise: reduce 4 split-k partials + xg, 2 cells per thread
        float hv0, hv1;
        {
            float gv[4][2];
#pragma unroll
            for (int g = 0; g < 4; g++) {
                float s0 = xv[g].x, s1 = xv[g].y;
#pragma unroll
                for (int w = 0; w < 4; w++) {
                    float2 pv2 = *(const float2*)&sgp[((w * 4 + g) * 64 + prow) * SGROW + 2 * pv];
                    s0 += pv2.x; s1 += pv2.y;
                }
                gv[g][0] = s0; gv[g][1] = s1;
            }
            float i0 = sigm(gv[0][0]), i1 = sigm(gv[0][1]);
            float f0 = sigm(gv[1][0]), f1 = sigm(gv[1][1]);
            float g0 = tanh_fast(gv[2][0]), g1 = tanh_fast(gv[2][1]);
            float o0 = sigm(gv[3][0]), o1 = sigm(gv[3][1]);
            c0 = c0 * f0 + i0 * g0;
            c1 = c1 * f1 + i1 * g1;
            hv0 = o0 * tanh_fast(c0);
            hv1 = o1 * tanh_fast(c1);
        }

        uint32_t P = pack_bf2(hv0, hv1);
        float q0 = hv0 - __bfloat162float(__float2bfloat16(hv0));
        float q1 = hv1 - __bfloat162float(__float2bfloat16(hv1));
        uint32_t Q = pack_bf2(q0, q1);

        uint4* hb = g_hfrag[rb ^ 1];
        uint32_t* d1 = (uint32_t*)(hb + ((size_t)bn * 16 + pmt) * 32 + plane) + comp;
        *d1 = P;
        uint32_t* d2 = (uint32_t*)(hb + ((size_t)(bn + 32) * 16 + pmt) * 32 + plane) + comp;
        *d2 = Q;

        if (t == TT - 1)
            *(float2*)(g_hfp + (size_t)grow * HH + ghid) = make_float2(hv0, hv1);

        // IVALL-free group barrier: release-RED arrival, volatile L2 poll.
        __syncthreads();
        if (tid == 0) {
            asm volatile("red.release.gpu.global.add.u32 [%0], 1;"
                         :: "l"(barp) : "memory");
            const unsigned target = (t + 1) * 32;
            while (*(volatile unsigned*)barp < target) {}
        }
        __syncthreads();
    }
}

// ---------------------------------------------------------------------------
__global__ __launch_bounds__(256) void fc_kernel(const float* __restrict__ Wfc,
                                                 const float* __restrict__ bfc,
                                                 float* __restrict__ out) {
    int warp = (blockIdx.x * blockDim.x + threadIdx.x) >> 5;
    int lane = threadIdx.x & 31;
    if (warp >= BB * OO) return;
    int b = warp / OO;
    int o = warp - b * OO;
    const float4* hr = reinterpret_cast<const float4*>(g_hfp + (size_t)b * HH);
    const float4* wr = reinterpret_cast<const float4*>(Wfc + (size_t)o * HH);
    float s = 0.0f;
#pragma unroll
    for (int k = 0; k < 4; k++) {
        float4 h4 = hr[lane + (k << 5)];
        float4 w4 = wr[lane + (k << 5)];
        s += h4.x * w4.x + h4.y * w4.y + h4.z * w4.z + h4.w * w4.w;
    }
#pragma unroll
    for (int off = 16; off; off >>= 1) s += __shfl_xor_sync(0xffffffffu, s, off);
    if (lane == 0) out[warp] = s + bfc[o];
}

// ---------------------------------------------------------------------------
extern "C" void kernel_launch(void* const* d_in, const int* in_sizes, int n_in,
                              void* d_out, int out_size) {
    const float* x   = (const float*)d_in[0];
    const float* Wx  = (const float*)d_in[1];
    const float* bx  = (const float*)d_in[2];
    const float* Wh  = (const float*)d_in[3];
    const float* bh  = (const float*)d_in[4];
    const float* Wfc = (const float*)d_in[5];
    const float* bfc = (const float*)d_in[6];
    float* out = (float*)d_out;

    prep_kernel<<<2048, 256>>>(Wh, Wx);
    xsplit_kernel<<<2048, 256>>>(x);

    {
        dim3 grid((TT * BB) / 128, GG / 128);   // (1000, 16)
        cudaFuncSetAttribute(xg_hmma, cudaFuncAttributeMaxDynamicSharedMemorySize, SMEM_XG);
        xg_hmma<<<grid, 256, SMEM_XG>>>(bx, bh);
    }

    cudaFuncSetAttribute(lstm_hmma, cudaFuncAttributeMaxDynamicSharedMemorySize, SMEM_LSTM);
    lstm_hmma<<<NBLK, 512, SMEM_LSTM>>>();

    fc_kernel<<<(BB * OO * 32 + 255) / 256, 256>>>(Wfc, bfc, out);
}

// round 17
// speedup vs baseline: 1.1034x; 1.1034x over previous
#include <cuda_runtime.h>
#include <cuda_bf16.h>
#include <math.h>
#include <cstdint>

#define BB 256
#define TT 500
#define II 256
#define HH 512
#define GG 2048
#define OO 100
#define NBLK 128

typedef unsigned long long ull;

// ------------------------- global scratch (no allocs) -----------------------
// x in A-fragment layout: [t][ktx (0-15 x1, 16-31 x2)][mt 0-15][lane]  (131MB)
__device__ uint4 g_xfrag[(size_t)TT * 32 * 16 * 32];
// Wx in B-fragment layout: [bn][ktx (0-15 Wx1, 16-31 Wx2)][nt][lane]   (2MB)
__device__ uint4 g_Wxfrag[32 * 32 * 4 * 32];
// Wh in B-fragment layout: [bn][kt (0-31 W1, 32-63 W2)][nt][lane]      (4MB)
__device__ uint4 g_Wfrag[32 * 64 * 4 * 32];
// h in A-fragment layout: [buf][kt (0-31 h1, 32-63 h2)][mt][lane]
__device__ uint4 g_hfrag[2][64 * 16 * 32];
__device__ float g_hfp[BB * HH];                        // fp32 h (for fc)
__device__ unsigned g_barc[4 * 32];                     // 4 group counters, 128B apart

// ------------------------- helpers ------------------------------------------
__device__ __forceinline__ float sigm(float x) { return 1.0f / (1.0f + __expf(-x)); }
__device__ __forceinline__ float tanh_fast(float x) { return 1.0f - 2.0f / (1.0f + __expf(2.0f * x)); }
__device__ __forceinline__ void mma_bf16(float* d, uint32_t a0, uint32_t a1, uint32_t a2,
                                         uint32_t a3, uint32_t b0, uint32_t b1) {
    asm volatile(
        "mma.sync.aligned.m16n8k16.row.col.f32.bf16.bf16.f32 "
        "{%0,%1,%2,%3}, {%4,%5,%6,%7}, {%8,%9}, {%0,%1,%2,%3};"
        : "+f"(d[0]), "+f"(d[1]), "+f"(d[2]), "+f"(d[3])
        : "r"(a0), "r"(a1), "r"(a2), "r"(a3), "r"(b0), "r"(b1));
}
__device__ __forceinline__ uint32_t pack_bf2(float a, float b) {
    __nv_bfloat162 v = __halves2bfloat162(__float2bfloat16(a), __float2bfloat16(b));
    return *reinterpret_cast<uint32_t*>(&v);
}

// ---------------------------------------------------------------------------
// Prep A: x -> A-fragment layout (hi + residual). Fragment element mapping
// (same as g_hfrag, deskchecked via R11 epilogue): for uint32 (reg, lane):
//   m' = (reg&1)*8 + lane/4 ;  k' = ((reg>>1)&1)*8 + 2*(lane&3)
//   b = mt*16 + m' ;  i = (ktx&15)*16 + k'
// ---------------------------------------------------------------------------
__global__ __launch_bounds__(256) void xfrag_kernel(const float* __restrict__ x) {
    const size_t total = (size_t)TT * 32 * 16 * 32 * 4;   // uint32 count
    const size_t stride = (size_t)gridDim.x * blockDim.x;
    for (size_t idx = (size_t)blockIdx.x * blockDim.x + threadIdx.x; idx < total; idx += stride) {
        int reg = idx & 3;
        int lane = (idx >> 2) & 31;
        int mt = (idx >> 7) & 15;
        int ktx = (idx >> 11) & 31;
        int t = (int)(idx >> 16);
        int mp = (reg & 1) * 8 + (lane >> 2);
        int kp = ((reg >> 1) & 1) * 8 + 2 * (lane & 3);
        int b = mt * 16 + mp;
        int i = (ktx & 15) * 16 + kp;
        const float* xp = x + ((size_t)b * TT + t) * II + i;
        float v0 = xp[0], v1 = xp[1];
        __nv_bfloat16 h0 = __float2bfloat16(v0), h1 = __float2bfloat16(v1);
        __nv_bfloat162 out;
        if (ktx < 16) out = __halves2bfloat162(h0, h1);
        else out = __halves2bfloat162(__float2bfloat16(v0 - __bfloat162float(h0)),
                                      __float2bfloat16(v1 - __bfloat162float(h1)));
        reinterpret_cast<__nv_bfloat162*>(g_xfrag)[idx] = out;
    }
}

// ---------------------------------------------------------------------------
// Prep B: Wh -> g_Wfrag (validated R8-R16), Wx -> g_Wxfrag (same formula,
// K=256), zero g_hfrag, reset group barriers.
// ---------------------------------------------------------------------------
__global__ __launch_bounds__(256) void prep_kernel(const float* __restrict__ Wh,
                                                   const float* __restrict__ Wx) {
    const int stride = gridDim.x * blockDim.x;
    const int tid0 = blockIdx.x * blockDim.x + threadIdx.x;

    // Wh fragments
    for (int idx = tid0; idx < 32 * 64 * 4 * 32 * 4; idx += stride) {
        int reg = idx & 3, lane = (idx >> 2) & 31, nt = (idx >> 7) & 3;
        int kt = (idx >> 9) & 63, bn = idx >> 15;
        int nl = nt * 16 + (reg & 1) * 8 + (lane >> 2);
        int kk = (kt & 31) * 16 + ((reg >> 1) & 1) * 8 + 2 * (lane & 3);
        int gate = (nl >> 3) & 3;
        int hidl = ((nl >> 5) << 3) + (nl & 7);
        int gcol = (gate << 9) + (bn << 4) + hidl;
        float w0 = Wh[(size_t)gcol * HH + kk];
        float w1 = Wh[(size_t)gcol * HH + kk + 1];
        __nv_bfloat16 h0 = __float2bfloat16(w0), h1 = __float2bfloat16(w1);
        __nv_bfloat162 v;
        if (kt < 32) v = __halves2bfloat162(h0, h1);
        else v = __halves2bfloat162(__float2bfloat16(w0 - __bfloat162float(h0)),
                                    __float2bfloat16(w1 - __bfloat162float(h1)));
        reinterpret_cast<__nv_bfloat162*>(g_Wfrag)[idx] = v;
    }

    // Wx fragments (K = 256)
    for (int idx = tid0; idx < 32 * 32 * 4 * 32 * 4; idx += stride) {
        int reg = idx & 3, lane = (idx >> 2) & 31, nt = (idx >> 7) & 3;
        int ktx = (idx >> 9) & 31, bn = idx >> 14;
        int nl = nt * 16 + (reg & 1) * 8 + (lane >> 2);
        int kk = (ktx & 15) * 16 + ((reg >> 1) & 1) * 8 + 2 * (lane & 3);
        int gate = (nl >> 3) & 3;
        int hidl = ((nl >> 5) << 3) + (nl & 7);
        int gcol = (gate << 9) + (bn << 4) + hidl;
        float w0 = Wx[(size_t)gcol * II + kk];
        float w1 = Wx[(size_t)gcol * II + kk + 1];
        __nv_bfloat16 h0 = __float2bfloat16(w0), h1 = __float2bfloat16(w1);
        __nv_bfloat162 v;
        if (ktx < 16) v = __halves2bfloat162(h0, h1);
        else v = __halves2bfloat162(__float2bfloat16(w0 - __bfloat162float(h0)),
                                    __float2bfloat16(w1 - __bfloat162float(h1)));
        reinterpret_cast<__nv_bfloat162*>(g_Wxfrag)[idx] = v;
    }

    for (int idx = tid0; idx < 2 * 64 * 16 * 32; idx += stride)
        reinterpret_cast<uint4*>(g_hfrag)[idx] = make_uint4(0, 0, 0, 0);

    if (tid0 < 4 * 32) g_barc[tid0] = 0;
}

// ---------------------------------------------------------------------------
// Kernel: persistent fused HMMA LSTM. 128 blocks x 512 threads.
// Block (bm, bn): 64 batch rows x 64 gate-cols. Warp (wm 0..3, wq 0..3):
// M16 tile wm, FULL N64, split-k: h-part kt [wq*8,+8), x-part ktx [wq*4,+4).
// gates[t] = h-terms (h1W1+h1W2+h2W1, K=512 each) + x-terms (x1Wx1+x1Wx2+
// x2Wx1, K=256 each) + bias. The x-part for step t+1 runs in the barrier
// wait window (independent of h). No g_xg buffer at all.
// Split-k partials reduced through 72KB smem at pointwise.
// Group barrier per bm: red.release.gpu arrive + volatile poll (IVALL-free).
// ---------------------------------------------------------------------------
#define SGROW 18
#define SMEM_LSTM (4 * 4 * 64 * SGROW * 4)   // 73728 B

__global__ __launch_bounds__(512, 1) void lstm_hmma(const float* __restrict__ bx,
                                                    const float* __restrict__ bh) {
    extern __shared__ float sgp[];   // [wq][gate][row][SGROW]

    const int tid = threadIdx.x;
    const int lane = tid & 31;
    const int wid = tid >> 5;
    const int wm = wid & 3;
    const int wq = wid >> 2;
    const int qp = lane >> 2;
    const int t4 = lane & 3;

    const int bm = blockIdx.x >> 5;
    const int bn = blockIdx.x & 31;
    const int m0 = bm << 6;
    const int j0 = bn << 4;
    const int mt = bm * 4 + wm;
    const int ktb = wq * 8;           // h-part kt base
    const int ktxb = wq * 4;          // x-part ktx base

    const int prow = tid >> 3;
    const int pv = tid & 7;
    const int grow = m0 + prow;
    const int ghid = j0 + 2 * pv;
    const int pmt = bm * 4 + (prow >> 4);
    const int r16 = prow & 15;
    const int comp = (r16 >> 3) + 2 * (pv >> 2);
    const int plane = (r16 & 7) * 4 + (pv & 3);

    unsigned* barp = &g_barc[bm * 32];

    // bias for this thread's pointwise cells (loaded once)
    float2 bias[4];
#pragma unroll
    for (int g = 0; g < 4; g++) {
        int col = (g << 9) + ghid;
        bias[g] = make_float2(bx[col] + bh[col], bx[col + 1] + bh[col + 1]);
    }

    float c0 = 0.f, c1 = 0.f;

    // 8 independent acc quads: [nt][p]; persists across the x/h boundary
    float acc[4][2][4] = {};

    // ---- x-part for t = 0
    {
        const uint4* Axf = g_xfrag + (size_t)0 * 16384 + (size_t)mt * 32 + lane;
        uint4 xa1[2], xa2[2];
#pragma unroll
        for (int j = 0; j < 2; j++) {
            xa1[j] = __ldcg(Axf + (size_t)(ktxb + j) * 512);
            xa2[j] = __ldcg(Axf + (size_t)(ktxb + j + 16) * 512);
        }
#pragma unroll
        for (int c = 0; c < 4; c++) {
            uint4 A1 = xa1[c & 1], A2 = xa2[c & 1];
            if (c < 2) {
                xa1[c & 1] = __ldcg(Axf + (size_t)(ktxb + c + 2) * 512);
                xa2[c & 1] = __ldcg(Axf + (size_t)(ktxb + c + 18) * 512);
            }
            const uint4* wxb = g_Wxfrag + (((size_t)bn * 32 + ktxb + c) * 4) * 32 + lane;
#pragma unroll
            for (int nt = 0; nt < 4; nt++) {
                uint4 B1 = wxb[nt * 32];
                uint4 B2 = wxb[16 * 4 * 32 + nt * 32];
                mma_bf16(acc[nt][0], A1.x, A1.y, A1.z, A1.w, B1.x, B1.z);
                mma_bf16(acc[nt][1], A1.x, A1.y, A1.z, A1.w, B1.y, B1.w);
                mma_bf16(acc[nt][0], A1.x, A1.y, A1.z, A1.w, B2.x, B2.z);
                mma_bf16(acc[nt][1], A1.x, A1.y, A1.z, A1.w, B2.y, B2.w);
                mma_bf16(acc[nt][0], A2.x, A2.y, A2.z, A2.w, B1.x, B1.z);
                mma_bf16(acc[nt][1], A2.x, A2.y, A2.z, A2.w, B1.y, B1.w);
            }
        }
    }

    for (int t = 0; t < TT; ++t) {
        const int rb = t & 1;

        // ---- h-part (accumulates onto x partials)
        {
            const uint4* Af = g_hfrag[rb] + (size_t)mt * 32 + lane;
            uint4 a1q[4], a2q[4];
#pragma unroll
            for (int j = 0; j < 4; j++) {
                a1q[j] = __ldcg(Af + (size_t)(ktb + j) * 512);
                a2q[j] = __ldcg(Af + (size_t)(ktb + j + 32) * 512);
            }
#pragma unroll
            for (int kt = 0; kt < 8; kt++) {
                uint4 A1 = a1q[kt & 3], A2 = a2q[kt & 3];
                if (kt < 4) {
                    a1q[kt & 3] = __ldcg(Af + (size_t)(ktb + kt + 4) * 512);
                    a2q[kt & 3] = __ldcg(Af + (size_t)(ktb + kt + 36) * 512);
                }
                const uint4* wbase = g_Wfrag + (((size_t)bn * 64 + ktb + kt) * 4) * 32 + lane;
#pragma unroll
                for (int nt = 0; nt < 4; nt++) {
                    uint4 B1 = wbase[nt * 32];
                    uint4 B2 = wbase[32 * 4 * 32 + nt * 32];
                    mma_bf16(acc[nt][0], A1.x, A1.y, A1.z, A1.w, B1.x, B1.z);
                    mma_bf16(acc[nt][1], A1.x, A1.y, A1.z, A1.w, B1.y, B1.w);
                    mma_bf16(acc[nt][0], A1.x, A1.y, A1.z, A1.w, B2.x, B2.z);
                    mma_bf16(acc[nt][1], A1.x, A1.y, A1.z, A1.w, B2.y, B2.w);
                    mma_bf16(acc[nt][0], A2.x, A2.y, A2.z, A2.w, B1.x, B1.z);
                    mma_bf16(acc[nt][1], A2.x, A2.y, A2.z, A2.w, B1.y, B1.w);
                }
            }
        }

        // stage split-k partial gates to smem: gate=(2nt+p)&3, hid base (nt>>1)*8
#pragma unroll
        for (int nt = 0; nt < 4; nt++) {
#pragma unroll
            for (int p = 0; p < 2; p++) {
                int gate = (2 * nt + p) & 3;
                int hidb = ((nt >> 1) << 3) + 2 * t4;
                float* s0 = &sgp[((wq * 4 + gate) * 64 + wm * 16 + qp) * SGROW + hidb];
                *(float2*)s0 = make_float2(acc[nt][p][0], acc[nt][p][1]);
                float* s1 = &sgp[((wq * 4 + gate) * 64 + wm * 16 + qp + 8) * SGROW + hidb];
                *(float2*)s1 = make_float2(acc[nt][p][2], acc[nt][p][3]);
            }
        }
        __syncthreads();

        // pointwise: reduce 4 split-k partials + bias, 2 cells per thread
        float hv0, hv1;
        {
            float gv[4][2];
#pragma unroll
            for (int g = 0; g < 4; g++) {
                float s0 = bias[g].x, s1 = bias[g].y;
#pragma unroll
                for (int w = 0; w < 4; w++) {
                    float2 pv2 = *(const float2*)&sgp[((w * 4 + g) * 64 + prow) * SGROW + 2 * pv];
                    s0 += pv2.x; s1 += pv2.y;
                }
                gv[g][0] = s0; gv[g][1] = s1;
            }
            float i0 = sigm(gv[0][0]), i1 = sigm(gv[0][1]);
            float f0 = sigm(gv[1][0]), f1 = sigm(gv[1][1]);
            float g0 = tanh_fast(gv[2][0]), g1 = tanh_fast(gv[2][1]);
            float o0 = sigm(gv[3][0]), o1 = sigm(gv[3][1]);
            c0 = c0 * f0 + i0 * g0;
            c1 = c1 * f1 + i1 * g1;
            hv0 = o0 * tanh_fast(c0);
            hv1 = o1 * tanh_fast(c1);
        }

        uint32_t P = pack_bf2(hv0, hv1);
        float q0 = hv0 - __bfloat162float(__float2bfloat16(hv0));
        float q1 = hv1 - __bfloat162float(__float2bfloat16(hv1));
        uint32_t Q = pack_bf2(q0, q1);

        uint4* hb = g_hfrag[rb ^ 1];
        uint32_t* d1 = (uint32_t*)(hb + ((size_t)bn * 16 + pmt) * 32 + plane) + comp;
        *d1 = P;
        uint32_t* d2 = (uint32_t*)(hb + ((size_t)(bn + 32) * 16 + pmt) * 32 + plane) + comp;
        *d2 = Q;

        if (t == TT - 1)
            *(float2*)(g_hfp + (size_t)grow * HH + ghid) = make_float2(hv0, hv1);

        // barrier arrive (IVALL-free), then x-part for t+1 fills the wait window
        __syncthreads();
        if (tid == 0) {
            asm volatile("red.release.gpu.global.add.u32 [%0], 1;"
                         :: "l"(barp) : "memory");
        }

        // ---- x-part for t+1 (independent of h; overlaps other blocks' arrivals)
#pragma unroll
        for (int nt = 0; nt < 4; nt++)
#pragma unroll
            for (int p = 0; p < 2; p++)
#pragma unroll
                for (int d = 0; d < 4; d++)
                    acc[nt][p][d] = 0.0f;

        if (t < TT - 1) {
            const uint4* Axf = g_xfrag + (size_t)(t + 1) * 16384 + (size_t)mt * 32 + lane;
            uint4 xa1[2], xa2[2];
#pragma unroll
            for (int j = 0; j < 2; j++) {
                xa1[j] = __ldcg(Axf + (size_t)(ktxb + j) * 512);
                xa2[j] = __ldcg(Axf + (size_t)(ktxb + j + 16) * 512);
            }
#pragma unroll
            for (int c = 0; c < 4; c++) {
                uint4 A1 = xa1[c & 1], A2 = xa2[c & 1];
                if (c < 2) {
                    xa1[c & 1] = __ldcg(Axf + (size_t)(ktxb + c + 2) * 512);
                    xa2[c & 1] = __ldcg(Axf + (size_t)(ktxb + c + 18) * 512);
                }
                const uint4* wxb = g_Wxfrag + (((size_t)bn * 32 + ktxb + c) * 4) * 32 + lane;
#pragma unroll
                for (int nt = 0; nt < 4; nt++) {
                    uint4 B1 = wxb[nt * 32];
                    uint4 B2 = wxb[16 * 4 * 32 + nt * 32];
                    mma_bf16(acc[nt][0], A1.x, A1.y, A1.z, A1.w, B1.x, B1.z);
                    mma_bf16(acc[nt][1], A1.x, A1.y, A1.z, A1.w, B1.y, B1.w);
                    mma_bf16(acc[nt][0], A1.x, A1.y, A1.z, A1.w, B2.x, B2.z);
                    mma_bf16(acc[nt][1], A1.x, A1.y, A1.z, A1.w, B2.y, B2.w);
                    mma_bf16(acc[nt][0], A2.x, A2.y, A2.z, A2.w, B1.x, B1.z);
                    mma_bf16(acc[nt][1], A2.x, A2.y, A2.z, A2.w, B1.y, B1.w);
                }
            }
        }

        // poll and release the step
        if (tid == 0) {
            const unsigned target = (t + 1) * 32;
            while (*(volatile unsigned*)barp < target) {}
        }
        __syncthreads();
    }
}

// ---------------------------------------------------------------------------
__global__ __launch_bounds__(256) void fc_kernel(const float* __restrict__ Wfc,
                                                 const float* __restrict__ bfc,
                                                 float* __restrict__ out) {
    int warp = (blockIdx.x * blockDim.x + threadIdx.x) >> 5;
    int lane = threadIdx.x & 31;
    if (warp >= BB * OO) return;
    int b = warp / OO;
    int o = warp - b * OO;
    const float4* hr = reinterpret_cast<const float4*>(g_hfp + (size_t)b * HH);
    const float4* wr = reinterpret_cast<const float4*>(Wfc + (size_t)o * HH);
    float s = 0.0f;
#pragma unroll
    for (int k = 0; k < 4; k++) {
        float4 h4 = hr[lane + (k << 5)];
        float4 w4 = wr[lane + (k << 5)];
        s += h4.x * w4.x + h4.y * w4.y + h4.z * w4.z + h4.w * w4.w;
    }
#pragma unroll
    for (int off = 16; off; off >>= 1) s += __shfl_xor_sync(0xffffffffu, s, off);
    if (lane == 0) out[warp] = s + bfc[o];
}

// ---------------------------------------------------------------------------
extern "C" void kernel_launch(void* const* d_in, const int* in_sizes, int n_in,
                              void* d_out, int out_size) {
    const float* x   = (const float*)d_in[0];
    const float* Wx  = (const float*)d_in[1];
    const float* bx  = (const float*)d_in[2];
    const float* Wh  = (const float*)d_in[3];
    const float* bh  = (const float*)d_in[4];
    const float* Wfc = (const float*)d_in[5];
    const float* bfc = (const float*)d_in[6];
    float* out = (float*)d_out;

    prep_kernel<<<2048, 256>>>(Wh, Wx);
    xfrag_kernel<<<8192, 256>>>(x);

    cudaFuncSetAttribute(lstm_hmma, cudaFuncAttributeMaxDynamicSharedMemorySize, SMEM_LSTM);
    lstm_hmma<<<NBLK, 512, SMEM_LSTM>>>(bx, bh);

    fc_kernel<<<(BB * OO * 32 + 255) / 256, 256>>>(Wfc, bfc, out);
}